// round 13
// baseline (speedup 1.0000x reference)
#include <cuda_runtime.h>
#include <cuda_fp16.h>
#include <cstdint>

// ================= config =================
#define THREADS 256        // 8 warps; warp grid 2(M of 32) x 4(N of 32)
#define SLICES 19          // 19 * 16 = 304 persistent CTAs = 2 per SM x 152 SMs
#define TILE_M 64          // nodes per tile
#define KDIM 128
#define NDIM 128
#define M_TOTAL 16
#define NPATH 4

// ================= helpers =================

__device__ __forceinline__ uint32_t smem_u32(const void* p) {
    uint32_t a;
    asm("{ .reg .u64 t; cvta.to.shared.u64 t, %1; cvt.u32.u64 %0, t; }"
        : "=r"(a) : "l"(p));
    return a;
}

#define LDMATRIX_X4(R0, R1, R2, R3, ADDR)                                  \
    asm volatile("ldmatrix.sync.aligned.m8n8.x4.shared.b16 {%0,%1,%2,%3}, [%4];" \
        : "=r"(R0), "=r"(R1), "=r"(R2), "=r"(R3) : "r"(ADDR))

#define MMA16816(D, A, B0, B1)                                             \
    asm volatile("mma.sync.aligned.m16n8k16.row.col.f32.f16.f16.f32 "      \
        "{%0,%1,%2,%3}, {%4,%5,%6,%7}, {%8,%9}, {%0,%1,%2,%3};"            \
        : "+f"((D)[0]), "+f"((D)[1]), "+f"((D)[2]), "+f"((D)[3])           \
        : "r"((A)[0]), "r"((A)[1]), "r"((A)[2]), "r"((A)[3]),              \
          "r"(B0), "r"(B1))

#define STS64(ADDR, LO, HI)                                                \
    asm volatile("st.shared.v2.b32 [%0], {%1,%2};"                          \
        :: "r"(ADDR), "r"(LO), "r"(HI) : "memory")

#define STS16(ADDR, H)                                                     \
    asm volatile("st.shared.b16 [%0], %1;"                                  \
        :: "r"(ADDR), "h"(H) : "memory")

#define LDS128(R0, R1, R2, R3, ADDR)                                       \
    asm volatile("ld.shared.v4.b32 {%0,%1,%2,%3}, [%4];"                    \
        : "=r"(R0), "=r"(R1), "=r"(R2), "=r"(R3) : "r"(ADDR))

#define CP_ASYNC16(DST, SRC, SZ)                                           \
    asm volatile("cp.async.cg.shared.global [%0], [%1], 16, %2;"            \
        :: "r"(DST), "l"(SRC), "r"(SZ) : "memory")

#define CP_COMMIT() asm volatile("cp.async.commit_group;" ::: "memory")
#define CP_WAIT1()  asm volatile("cp.async.wait_group 1;" ::: "memory")

// ================= main kernel =================
// Single-kernel graph: W conversion folded into the prologue (W is L2-resident).
// smem (96KB): F0/F1 = 16KB fp16 mma bufs (swizzled), S0/S1 = 32KB fp32 stage.
// pipeline per iter: cp.async(i+2) -> MMA(i) -> epilogue(i) -> wait -> convert(i+1).
// B[p] (128x128 fp16) lives in registers: breg[8][2][4] = 64 regs/thread.

__global__ void __launch_bounds__(THREADS, 2)
irreps_pers_kernel(const float* __restrict__ x,
                   const float* __restrict__ w,
                   const int* __restrict__ seg,
                   float* __restrict__ out,
                   int n_nodes, int ntiles) {
    extern __shared__ char smem[];

    const int tid = threadIdx.x;
    const int lane = tid & 31;
    const int wid = tid >> 5;
    const int m = blockIdx.y;
    const int s = blockIdx.x;
    const int p = seg[m];

    const uint32_t sF0 = smem_u32(smem);
    const uint32_t sF1 = sF0 + 16384u;
    const uint32_t sS0 = sF0 + 32768u;
    const uint32_t sS1 = sF0 + 65536u;

    // warp tile: 32 rows x 32 cols
    const int wr = (wid >> 2) * 32;
    const int wc = (wid & 3) * 32;

    const int cnt = (ntiles - s + SLICES - 1) / SLICES;

    // staging coords: row = u*8 + rsub (rsub = wid), 16B col = fc (= lane)
    const int fc = lane;
    const int rsub = wid;
    const uint32_t swz = (uint32_t)((((fc >> 1) ^ (rsub & 7)) << 4) | ((fc & 1) << 3));

    // ---- prologue: cp.async tile 0 -> S0 (starts DRAM stream immediately) ----
    {
        const int nb = s * TILE_M;
        #pragma unroll
        for (int u = 0; u < 8; ++u) {
            int row = u * 8 + rsub;
            int node = nb + row;
            uint32_t sz = (node < n_nodes) ? 16u : 0u;
            int node_c = (node < n_nodes) ? node : 0;
            const char* src = reinterpret_cast<const char*>(
                x + (((size_t)node_c * M_TOTAL + m) << 7)) + fc * 16;
            CP_ASYNC16(sS0 + (uint32_t)(row << 9) + (uint32_t)(fc << 4), src, sz);
        }
        CP_COMMIT();
    }

    // ---- convert W[p] fp32 [k][n] -> S1 fp16 [n][k] swizzled (in-kernel, no prep) ----
    {
        const float* wp = w + (p << 14);
        #pragma unroll 8
        for (int i = 0; i < 64; ++i) {
            int e = i * THREADS + tid;        // 16384 elements, coalesced read
            int k = e >> 7;
            int n = e & 127;
            __half h = __float2half_rn(wp[e]);
            uint32_t off = (uint32_t)(n << 8)
                         + (uint32_t)((((k >> 3) ^ (n & 7)) << 4))
                         + (uint32_t)((k & 7) << 1);
            STS16(sS1 + off, __half_as_ushort(h));
        }
    }
    __syncthreads();

    // ---- LDSM B fragments into registers ----
    const int b_row = wc + (lane & 7) + ((lane >> 4) << 3);
    const uint32_t b_base = sS1 + (uint32_t)(b_row << 8);
    const int b_sw = b_row & 7;
    const int b_hi = (lane >> 3) & 1;

    uint32_t breg[8][2][4];
    #pragma unroll
    for (int ks = 0; ks < 8; ++ks) {
        const int bch = (2 * ks + b_hi) ^ b_sw;
        #pragma unroll
        for (int nt4 = 0; nt4 < 2; ++nt4)
            LDMATRIX_X4(breg[ks][nt4][0], breg[ks][nt4][1],
                        breg[ks][nt4][2], breg[ks][nt4][3],
                        b_base + (uint32_t)(nt4 << 12) + (uint32_t)(bch << 4));
    }
    __syncthreads();   // B reads done before S1 reused as stage buffer

    // ---- cp.async tile 1 -> S1 ----
    if (cnt > 1) {
        const int nb = (s + SLICES) * TILE_M;
        #pragma unroll
        for (int u = 0; u < 8; ++u) {
            int row = u * 8 + rsub;
            int node = nb + row;
            uint32_t sz = (node < n_nodes) ? 16u : 0u;
            int node_c = (node < n_nodes) ? node : 0;
            const char* src = reinterpret_cast<const char*>(
                x + (((size_t)node_c * M_TOTAL + m) << 7)) + fc * 16;
            CP_ASYNC16(sS1 + (uint32_t)(row << 9) + (uint32_t)(fc << 4), src, sz);
        }
    }
    CP_COMMIT();

    // ---- A fragment addressing ----
    const int a_hi = lane >> 4;
    const int a_sw = lane & 7;
    uint32_t aoff[2];
    #pragma unroll
    for (int mt = 0; mt < 2; ++mt)
        aoff[mt] = (uint32_t)((wr + mt * 16 + (lane & 15)) << 8);

    // ---- prologue: convert tile 0 (S0 -> F0) ----
    CP_WAIT1();
    #pragma unroll
    for (int u = 0; u < 8; ++u) {
        int row = u * 8 + rsub;
        uint32_t r0, r1, r2, r3;
        LDS128(r0, r1, r2, r3, sS0 + (uint32_t)(row << 9) + (uint32_t)(fc << 4));
        __half2 h0 = __floats2half2_rn(__uint_as_float(r0), __uint_as_float(r1));
        __half2 h1 = __floats2half2_rn(__uint_as_float(r2), __uint_as_float(r3));
        STS64(sF0 + (uint32_t)(row << 8) + swz,
              *reinterpret_cast<uint32_t*>(&h0),
              *reinterpret_cast<uint32_t*>(&h1));
    }
    __syncthreads();

    // ================= main loop =================
    for (int i = 0; i < cnt; ++i) {
        const int j = i & 1;
        const int t = s + i * SLICES;
        const uint32_t sF = j ? sF1 : sF0;

        // ---- issue cp.async tile i+2 -> S(i&1) (non-blocking) ----
        if (i + 2 < cnt) {
            const uint32_t sS = j ? sS1 : sS0;
            const int nb = (s + (i + 2) * SLICES) * TILE_M;
            #pragma unroll
            for (int u = 0; u < 8; ++u) {
                int row = u * 8 + rsub;
                int node = nb + row;
                uint32_t sz = (node < n_nodes) ? 16u : 0u;
                int node_c = (node < n_nodes) ? node : 0;
                const char* src = reinterpret_cast<const char*>(
                    x + (((size_t)node_c * M_TOTAL + m) << 7)) + fc * 16;
                CP_ASYNC16(sS + (uint32_t)(row << 9) + (uint32_t)(fc << 4), src, sz);
            }
        }
        CP_COMMIT();   // keep group counts aligned

        // ---- MMA on tile i from F(i&1) ----
        float acc[2][4][4];
        #pragma unroll
        for (int mt = 0; mt < 2; ++mt)
            #pragma unroll
            for (int nt = 0; nt < 4; ++nt)
                #pragma unroll
                for (int q = 0; q < 4; ++q)
                    acc[mt][nt][q] = 0.0f;

        #pragma unroll
        for (int ks = 0; ks < 8; ++ks) {
            const int ach = (2 * ks + a_hi) ^ a_sw;
            uint32_t a[2][4];
            #pragma unroll
            for (int mt = 0; mt < 2; ++mt)
                LDMATRIX_X4(a[mt][0], a[mt][1], a[mt][2], a[mt][3],
                            sF + aoff[mt] + (uint32_t)(ach << 4));
            #pragma unroll
            for (int mt = 0; mt < 2; ++mt)
                #pragma unroll
                for (int nt = 0; nt < 4; ++nt)
                    MMA16816(acc[mt][nt], a[mt],
                             breg[ks][nt >> 1][(nt & 1) * 2],
                             breg[ks][nt >> 1][(nt & 1) * 2 + 1]);
        }

        // ---- epilogue: store tile i ----
        {
            const int node0 = t * TILE_M;
            const int row_in = lane >> 2;
            const int col_in = (lane & 3) << 1;
            #pragma unroll
            for (int mt = 0; mt < 2; ++mt) {
                #pragma unroll
                for (int q2 = 0; q2 < 2; ++q2) {
                    int node = node0 + wr + mt * 16 + q2 * 8 + row_in;
                    if (node < n_nodes) {
                        float* op = out + (((size_t)node * M_TOTAL + m) << 7)
                                  + wc + col_in;
                        #pragma unroll
                        for (int nt = 0; nt < 4; ++nt) {
                            float2 v;
                            v.x = acc[mt][nt][q2 * 2];
                            v.y = acc[mt][nt][q2 * 2 + 1];
                            *reinterpret_cast<float2*>(op + nt * 8) = v;
                        }
                    }
                }
            }
        }

        // ---- wait tile i+1, convert S((i+1)&1) -> F((i+1)&1) ----
        CP_WAIT1();
        if (i + 1 < cnt) {
            const uint32_t sSn = j ? sS0 : sS1;
            const uint32_t sFn = j ? sF0 : sF1;
            #pragma unroll
            for (int u = 0; u < 8; ++u) {
                int row = u * 8 + rsub;
                uint32_t r0, r1, r2, r3;
                LDS128(r0, r1, r2, r3, sSn + (uint32_t)(row << 9) + (uint32_t)(fc << 4));
                __half2 h0 = __floats2half2_rn(__uint_as_float(r0), __uint_as_float(r1));
                __half2 h1 = __floats2half2_rn(__uint_as_float(r2), __uint_as_float(r3));
                STS64(sFn + (uint32_t)(row << 8) + swz,
                      *reinterpret_cast<uint32_t*>(&h0),
                      *reinterpret_cast<uint32_t*>(&h1));
            }
        }
        __syncthreads();
    }
}

// ================= launch =================

extern "C" void kernel_launch(void* const* d_in, const int* in_sizes, int n_in,
                              void* d_out, int out_size) {
    const float* x   = (const float*)d_in[0];
    const float* w   = (const float*)d_in[1];
    const int*   seg = (const int*)d_in[2];
    float* out = (float*)d_out;

    int n_nodes = in_sizes[0] / (M_TOTAL * KDIM);     // 50000
    int ntiles = (n_nodes + TILE_M - 1) / TILE_M;     // 782

    static bool attr_set = false;
    if (!attr_set) {
        cudaFuncSetAttribute(irreps_pers_kernel,
                             cudaFuncAttributeMaxDynamicSharedMemorySize, 98304);
        attr_set = true;
    }

    dim3 grid(SLICES, M_TOTAL);   // 19 x 16 = 304 persistent CTAs (2/SM x 152 SMs)
    irreps_pers_kernel<<<grid, THREADS, 98304>>>(x, w, seg, out, n_nodes, ntiles);
}

// round 14
// speedup vs baseline: 1.0167x; 1.0167x over previous
#include <cuda_runtime.h>
#include <cuda_fp16.h>
#include <cstdint>

// ================= config =================
#define THREADS 512        // 16 warps; warp grid 4(M of 32) x 4(N of 32)
#define NCTAS 152          // flat persistent grid: 1 CTA per SM on GB300
#define TILE_M 128         // nodes per tile
#define KDIM 128
#define NDIM 128
#define M_TOTAL 16
#define NPATH 4

// smem layout (bytes from base): B 32K | F0 32K | F1 32K | S0 64K | S1 64K = 224K
#define OFF_F0 32768u
#define OFF_F1 65536u
#define OFF_S0 98304u
#define OFF_S1 163840u
#define SMEM_BYTES 229376u

// ================= helpers =================

__device__ __forceinline__ uint32_t smem_u32(const void* p) {
    uint32_t a;
    asm("{ .reg .u64 t; cvta.to.shared.u64 t, %1; cvt.u32.u64 %0, t; }"
        : "=r"(a) : "l"(p));
    return a;
}

#define LDMATRIX_X4(R0, R1, R2, R3, ADDR)                                  \
    asm volatile("ldmatrix.sync.aligned.m8n8.x4.shared.b16 {%0,%1,%2,%3}, [%4];" \
        : "=r"(R0), "=r"(R1), "=r"(R2), "=r"(R3) : "r"(ADDR))

#define MMA16816(D, A, B0, B1)                                             \
    asm volatile("mma.sync.aligned.m16n8k16.row.col.f32.f16.f16.f32 "      \
        "{%0,%1,%2,%3}, {%4,%5,%6,%7}, {%8,%9}, {%0,%1,%2,%3};"            \
        : "+f"((D)[0]), "+f"((D)[1]), "+f"((D)[2]), "+f"((D)[3])           \
        : "r"((A)[0]), "r"((A)[1]), "r"((A)[2]), "r"((A)[3]),              \
          "r"(B0), "r"(B1))

#define STS64(ADDR, LO, HI)                                                \
    asm volatile("st.shared.v2.b32 [%0], {%1,%2};"                          \
        :: "r"(ADDR), "r"(LO), "r"(HI) : "memory")

#define STS16(ADDR, H)                                                     \
    asm volatile("st.shared.b16 [%0], %1;"                                  \
        :: "r"(ADDR), "h"(H) : "memory")

#define LDS128(R0, R1, R2, R3, ADDR)                                       \
    asm volatile("ld.shared.v4.b32 {%0,%1,%2,%3}, [%4];"                    \
        : "=r"(R0), "=r"(R1), "=r"(R2), "=r"(R3) : "r"(ADDR))

#define CP_ASYNC16(DST, SRC, SZ)                                           \
    asm volatile("cp.async.cg.shared.global [%0], [%1], 16, %2;"            \
        :: "r"(DST), "l"(SRC), "r"(SZ) : "memory")

#define CP_COMMIT() asm volatile("cp.async.commit_group;" ::: "memory")
#define CP_WAIT1()  asm volatile("cp.async.wait_group 1;" ::: "memory")

// ================= main kernel =================
// Flat persistent: 152 CTAs, unit list u = m*nt + t (m-major), contiguous range
// per CTA -> at most one m change per CTA (B restage from L2, dedicated buffer).
// Pipeline per iter: cp.async(u+2) -> [B restage if m changed] -> MMA(u) ->
// epilogue(u) -> wait -> convert(u+1) -> sync.

__global__ void __launch_bounds__(THREADS, 1)
irreps_flat_kernel(const float* __restrict__ x,
                   const float* __restrict__ w,
                   const int* __restrict__ seg,
                   float* __restrict__ out,
                   int n_nodes, int nt) {
    extern __shared__ char smem[];
    const uint32_t sB = smem_u32(smem);
    const uint32_t sF0 = sB + OFF_F0;
    const uint32_t sF1 = sB + OFF_F1;
    const uint32_t sS0 = sB + OFF_S0;
    const uint32_t sS1 = sB + OFF_S1;

    const int tid = threadIdx.x;
    const int lane = tid & 31;
    const int wid = tid >> 5;

    // warp tile: 32 rows x 32 cols (4x4 warp grid)
    const int wr = (wid >> 2) * 32;
    const int wc = (wid & 3) * 32;

    // unit range for this CTA
    const int total = nt * M_TOTAL;                         // 6256
    const int start = (int)(((long long)blockIdx.x * total) / NCTAS);
    const int end   = (int)(((long long)(blockIdx.x + 1) * total) / NCTAS);
    const int cnt = end - start;

    // cursors
    int mi = start / nt, ti = start - mi * nt;              // unit i
    int mp = mi, tp = ti;                                   // unit i+2
    // advance mp/tp by 2
    #pragma unroll
    for (int z = 0; z < 2; ++z) { if (++tp == nt) { tp = 0; ++mp; } }

    // staging coords: row = u*16 + rsub, 16B col = fc
    const int fc = lane;
    const int rsub = wid;
    const uint32_t swz = (uint32_t)((((fc >> 1) ^ (rsub & 7)) << 4) | ((fc & 1) << 3));

    // ---- cp.async tile for unit (m,t) into stage buffer sS ----
    auto load_tile = [&](int m, int t, uint32_t sS) {
        const int nb = t * TILE_M;
        #pragma unroll
        for (int u = 0; u < 8; ++u) {
            int row = u * 16 + rsub;
            int node = nb + row;
            uint32_t sz = (node < n_nodes) ? 16u : 0u;
            int node_c = (node < n_nodes) ? node : 0;
            const char* src = reinterpret_cast<const char*>(
                x + (((size_t)node_c * M_TOTAL + m) << 7)) + fc * 16;
            CP_ASYNC16(sS + (uint32_t)(row << 9) + (uint32_t)(fc << 4), src, sz);
        }
    };

    // ---- stage W[seg(m)] fp32 [k][n] -> sB fp16 [n][k] swizzled ----
    auto stage_B = [&](int m) {
        const int p = seg[m];
        const float* wp = w + (p << 14);
        #pragma unroll 8
        for (int i = 0; i < 32; ++i) {
            int e = i * THREADS + tid;          // 16384 elements
            int k = e >> 7;
            int n = e & 127;
            __half h = __float2half_rn(wp[e]);
            uint32_t off = (uint32_t)(n << 8)
                         + (uint32_t)((((k >> 3) ^ (n & 7)) << 4))
                         + (uint32_t)((k & 7) << 1);
            STS16(sB + off, __half_as_ushort(h));
        }
    };

    // ---- B fragment LDSM ----
    const int b_row = wc + (lane & 7) + ((lane >> 4) << 3);
    const uint32_t b_base = sB + (uint32_t)(b_row << 8);
    const int b_sw = b_row & 7;
    const int b_hi = (lane >> 3) & 1;
    uint32_t breg[8][2][4];
    auto ldsm_B = [&]() {
        #pragma unroll
        for (int ks = 0; ks < 8; ++ks) {
            const int bch = (2 * ks + b_hi) ^ b_sw;
            #pragma unroll
            for (int nt4 = 0; nt4 < 2; ++nt4)
                LDMATRIX_X4(breg[ks][nt4][0], breg[ks][nt4][1],
                            breg[ks][nt4][2], breg[ks][nt4][3],
                            b_base + (uint32_t)(nt4 << 12) + (uint32_t)(bch << 4));
        }
    };

    // ---- convert stage buffer (fp32) -> mma buffer (fp16, swizzled) ----
    auto convert_tile = [&](uint32_t sS, uint32_t sF) {
        #pragma unroll
        for (int u = 0; u < 8; ++u) {
            int row = u * 16 + rsub;
            uint32_t r0, r1, r2, r3;
            LDS128(r0, r1, r2, r3, sS + (uint32_t)(row << 9) + (uint32_t)(fc << 4));
            __half2 h0 = __floats2half2_rn(__uint_as_float(r0), __uint_as_float(r1));
            __half2 h1 = __floats2half2_rn(__uint_as_float(r2), __uint_as_float(r3));
            STS64(sF + (uint32_t)(row << 8) + swz,
                  *reinterpret_cast<uint32_t*>(&h0),
                  *reinterpret_cast<uint32_t*>(&h1));
        }
    };

    // ---- prologue ----
    load_tile(mi, ti, sS0);
    CP_COMMIT();
    stage_B(mi);
    int cur_m = mi;
    __syncthreads();
    ldsm_B();

    {   // cp.async unit 1 -> S1
        int m1 = mi, t1 = ti;
        if (++t1 == nt) { t1 = 0; ++m1; }
        if (cnt > 1) load_tile(m1, t1, sS1);
        CP_COMMIT();
    }

    // ---- A fragment addressing ----
    const int a_hi = lane >> 4;
    const int a_sw = lane & 7;
    uint32_t aoff[2];
    #pragma unroll
    for (int mt = 0; mt < 2; ++mt)
        aoff[mt] = (uint32_t)((wr + mt * 16 + (lane & 15)) << 8);

    CP_WAIT1();
    convert_tile(sS0, sF0);
    __syncthreads();

    // ================= main loop =================
    for (int i = 0; i < cnt; ++i) {
        const int j = i & 1;
        const uint32_t sF = j ? sF1 : sF0;

        // ---- issue cp.async unit i+2 ----
        if (i + 2 < cnt) load_tile(mp, tp, j ? sS1 : sS0);
        CP_COMMIT();

        // ---- B restage on m boundary (<=1 per CTA) ----
        if (mi != cur_m) {
            stage_B(mi);
            __syncthreads();
            ldsm_B();
            cur_m = mi;
        }

        // ---- MMA on unit i from F(j) ----
        float acc[2][4][4];
        #pragma unroll
        for (int mt = 0; mt < 2; ++mt)
            #pragma unroll
            for (int ntx = 0; ntx < 4; ++ntx)
                #pragma unroll
                for (int q = 0; q < 4; ++q)
                    acc[mt][ntx][q] = 0.0f;

        #pragma unroll
        for (int ks = 0; ks < 8; ++ks) {
            const int ach = (2 * ks + a_hi) ^ a_sw;
            uint32_t a[2][4];
            #pragma unroll
            for (int mt = 0; mt < 2; ++mt)
                LDMATRIX_X4(a[mt][0], a[mt][1], a[mt][2], a[mt][3],
                            sF + aoff[mt] + (uint32_t)(ach << 4));
            #pragma unroll
            for (int mt = 0; mt < 2; ++mt)
                #pragma unroll
                for (int ntx = 0; ntx < 4; ++ntx)
                    MMA16816(acc[mt][ntx], a[mt],
                             breg[ks][ntx >> 1][(ntx & 1) * 2],
                             breg[ks][ntx >> 1][(ntx & 1) * 2 + 1]);
        }

        // ---- epilogue: store unit i ----
        {
            const int node0 = ti * TILE_M;
            const int row_in = lane >> 2;
            const int col_in = (lane & 3) << 1;
            #pragma unroll
            for (int mt = 0; mt < 2; ++mt) {
                #pragma unroll
                for (int q2 = 0; q2 < 2; ++q2) {
                    int node = node0 + wr + mt * 16 + q2 * 8 + row_in;
                    if (node < n_nodes) {
                        float* op = out + (((size_t)node * M_TOTAL + mi) << 7)
                                  + wc + col_in;
                        #pragma unroll
                        for (int ntx = 0; ntx < 4; ++ntx) {
                            float2 v;
                            v.x = acc[mt][ntx][q2 * 2];
                            v.y = acc[mt][ntx][q2 * 2 + 1];
                            *reinterpret_cast<float2*>(op + ntx * 8) = v;
                        }
                    }
                }
            }
        }

        // ---- wait unit i+1, convert into F(j^1) ----
        CP_WAIT1();
        if (i + 1 < cnt)
            convert_tile(j ? sS0 : sS1, j ? sF0 : sF1);
        __syncthreads();

        // advance cursors
        if (++ti == nt) { ti = 0; ++mi; }
        if (++tp == nt) { tp = 0; ++mp; }
    }
}

// ================= launch =================

extern "C" void kernel_launch(void* const* d_in, const int* in_sizes, int n_in,
                              void* d_out, int out_size) {
    const float* x   = (const float*)d_in[0];
    const float* w   = (const float*)d_in[1];
    const int*   seg = (const int*)d_in[2];
    float* out = (float*)d_out;

    int n_nodes = in_sizes[0] / (M_TOTAL * KDIM);     // 50000
    int nt = (n_nodes + TILE_M - 1) / TILE_M;         // 391

    cudaFuncSetAttribute(irreps_flat_kernel,
                         cudaFuncAttributeMaxDynamicSharedMemorySize, SMEM_BYTES);

    irreps_flat_kernel<<<NCTAS, THREADS, SMEM_BYTES>>>(x, w, seg, out, n_nodes, nt);
}

// round 15
// speedup vs baseline: 1.0745x; 1.0568x over previous
#include <cuda_runtime.h>
#include <cuda_fp16.h>
#include <cstdint>

// ================= config =================
#define THREADS 512        // 2 independent groups of 8 warps (256 thr each)
#define VSLICES 19         // 19 * 16 = 304 virtual CTAs = 152 blocks * 2 groups
#define TILE_M 64          // nodes per tile (per group)
#define KDIM 128
#define NDIM 128
#define M_TOTAL 16
#define NPATH 4
#define GROUP_SMEM 98304u  // F0 16K | F1 16K | S0 32K | S1 32K per group

// ================= helpers =================

__device__ __forceinline__ uint32_t smem_u32(const void* p) {
    uint32_t a;
    asm("{ .reg .u64 t; cvta.to.shared.u64 t, %1; cvt.u32.u64 %0, t; }"
        : "=r"(a) : "l"(p));
    return a;
}

#define BAR_SYNC(ID)                                                       \
    asm volatile("bar.sync %0, 256;" :: "r"(ID) : "memory")

#define LDMATRIX_X4(R0, R1, R2, R3, ADDR)                                  \
    asm volatile("ldmatrix.sync.aligned.m8n8.x4.shared.b16 {%0,%1,%2,%3}, [%4];" \
        : "=r"(R0), "=r"(R1), "=r"(R2), "=r"(R3) : "r"(ADDR))

#define MMA16816(D, A, B0, B1)                                             \
    asm volatile("mma.sync.aligned.m16n8k16.row.col.f32.f16.f16.f32 "      \
        "{%0,%1,%2,%3}, {%4,%5,%6,%7}, {%8,%9}, {%0,%1,%2,%3};"            \
        : "+f"((D)[0]), "+f"((D)[1]), "+f"((D)[2]), "+f"((D)[3])           \
        : "r"((A)[0]), "r"((A)[1]), "r"((A)[2]), "r"((A)[3]),              \
          "r"(B0), "r"(B1))

#define STS64(ADDR, LO, HI)                                                \
    asm volatile("st.shared.v2.b32 [%0], {%1,%2};"                          \
        :: "r"(ADDR), "r"(LO), "r"(HI) : "memory")

#define STS16(ADDR, H)                                                     \
    asm volatile("st.shared.b16 [%0], %1;"                                  \
        :: "r"(ADDR), "h"(H) : "memory")

#define LDS128(R0, R1, R2, R3, ADDR)                                       \
    asm volatile("ld.shared.v4.b32 {%0,%1,%2,%3}, [%4];"                    \
        : "=r"(R0), "=r"(R1), "=r"(R2), "=r"(R3) : "r"(ADDR))

#define CP_ASYNC16(DST, SRC, SZ)                                           \
    asm volatile("cp.async.cg.shared.global [%0], [%1], 16, %2;"            \
        :: "r"(DST), "l"(SRC), "r"(SZ) : "memory")

#define CP_COMMIT() asm volatile("cp.async.commit_group;" ::: "memory")
#define CP_WAIT1()  asm volatile("cp.async.wait_group 1;" ::: "memory")

// ================= main kernel =================
// 152 blocks x 512 threads; each block hosts TWO independent 256-thread
// pipelines (named barriers), each identical to the R12 64x128-tile kernel:
// smem/group: F0/F1 16KB fp16 (swizzled), S0/S1 32KB fp32 stage.
// per-iter: cp.async(i+2) -> MMA(i) -> epilogue(i) -> wait -> convert(i+1).
// B[p] in registers: breg[8][2][4] = 64 regs/thread.

__global__ void __launch_bounds__(THREADS, 1)
irreps_dual_kernel(const float* __restrict__ x,
                   const float* __restrict__ w,
                   const int* __restrict__ seg,
                   float* __restrict__ out,
                   int n_nodes, int ntiles) {
    extern __shared__ char smem[];

    const int tid = threadIdx.x;
    const int g = tid >> 8;            // group 0 / 1
    const int tg = tid & 255;          // tid within group
    const int lane = tg & 31;
    const int wid = tg >> 5;           // 0..7 within group
    const int bar_id = 1 + g;

    // virtual CTA: v in [0, 304)
    const int v = (blockIdx.x << 1) | g;
    const int s = v % VSLICES;
    const int m = v / VSLICES;
    const int p = seg[m];

    const uint32_t base = smem_u32(smem) + (uint32_t)g * GROUP_SMEM;
    const uint32_t sF0 = base;
    const uint32_t sF1 = base + 16384u;
    const uint32_t sS0 = base + 32768u;
    const uint32_t sS1 = base + 65536u;

    // warp tile: 32 rows x 32 cols (2x4 warp grid per group, CTA-tile 64x128)
    const int wr = (wid >> 2) * 32;
    const int wc = (wid & 3) * 32;

    const int cnt = (ntiles - s + VSLICES - 1) / VSLICES;

    // staging coords: row = u*8 + rsub (rsub = wid), 16B col = fc (= lane)
    const int fc = lane;
    const int rsub = wid;
    const uint32_t swz = (uint32_t)((((fc >> 1) ^ (rsub & 7)) << 4) | ((fc & 1) << 3));

    // ---- prologue: cp.async tile 0 -> S0 ----
    {
        const int nb = s * TILE_M;
        #pragma unroll
        for (int u = 0; u < 8; ++u) {
            int row = u * 8 + rsub;
            int node = nb + row;
            uint32_t sz = (node < n_nodes) ? 16u : 0u;
            int node_c = (node < n_nodes) ? node : 0;
            const char* src = reinterpret_cast<const char*>(
                x + (((size_t)node_c * M_TOTAL + m) << 7)) + fc * 16;
            CP_ASYNC16(sS0 + (uint32_t)(row << 9) + (uint32_t)(fc << 4), src, sz);
        }
        CP_COMMIT();
    }

    // ---- convert W[p] fp32 [k][n] -> S1 fp16 [n][k] swizzled ----
    {
        const float* wp = w + (p << 14);
        #pragma unroll 8
        for (int i = 0; i < 64; ++i) {
            int e = i * 256 + tg;             // 16384 elements, coalesced
            int k = e >> 7;
            int n = e & 127;
            __half h = __float2half_rn(wp[e]);
            uint32_t off = (uint32_t)(n << 8)
                         + (uint32_t)((((k >> 3) ^ (n & 7)) << 4))
                         + (uint32_t)((k & 7) << 1);
            STS16(sS1 + off, __half_as_ushort(h));
        }
    }
    BAR_SYNC(bar_id);

    // ---- LDSM B fragments into registers ----
    const int b_row = wc + (lane & 7) + ((lane >> 4) << 3);
    const uint32_t b_base = sS1 + (uint32_t)(b_row << 8);
    const int b_sw = b_row & 7;
    const int b_hi = (lane >> 3) & 1;

    uint32_t breg[8][2][4];
    #pragma unroll
    for (int ks = 0; ks < 8; ++ks) {
        const int bch = (2 * ks + b_hi) ^ b_sw;
        #pragma unroll
        for (int nt4 = 0; nt4 < 2; ++nt4)
            LDMATRIX_X4(breg[ks][nt4][0], breg[ks][nt4][1],
                        breg[ks][nt4][2], breg[ks][nt4][3],
                        b_base + (uint32_t)(nt4 << 12) + (uint32_t)(bch << 4));
    }
    BAR_SYNC(bar_id);   // B reads done before S1 reused as stage buffer

    // ---- cp.async tile 1 -> S1 ----
    if (cnt > 1) {
        const int nb = (s + VSLICES) * TILE_M;
        #pragma unroll
        for (int u = 0; u < 8; ++u) {
            int row = u * 8 + rsub;
            int node = nb + row;
            uint32_t sz = (node < n_nodes) ? 16u : 0u;
            int node_c = (node < n_nodes) ? node : 0;
            const char* src = reinterpret_cast<const char*>(
                x + (((size_t)node_c * M_TOTAL + m) << 7)) + fc * 16;
            CP_ASYNC16(sS1 + (uint32_t)(row << 9) + (uint32_t)(fc << 4), src, sz);
        }
    }
    CP_COMMIT();

    // ---- A fragment addressing ----
    const int a_hi = lane >> 4;
    const int a_sw = lane & 7;
    uint32_t aoff[2];
    #pragma unroll
    for (int mt = 0; mt < 2; ++mt)
        aoff[mt] = (uint32_t)((wr + mt * 16 + (lane & 15)) << 8);

    // ---- prologue: convert tile 0 (S0 -> F0) ----
    CP_WAIT1();
    #pragma unroll
    for (int u = 0; u < 8; ++u) {
        int row = u * 8 + rsub;
        uint32_t r0, r1, r2, r3;
        LDS128(r0, r1, r2, r3, sS0 + (uint32_t)(row << 9) + (uint32_t)(fc << 4));
        __half2 h0 = __floats2half2_rn(__uint_as_float(r0), __uint_as_float(r1));
        __half2 h1 = __floats2half2_rn(__uint_as_float(r2), __uint_as_float(r3));
        STS64(sF0 + (uint32_t)(row << 8) + swz,
              *reinterpret_cast<uint32_t*>(&h0),
              *reinterpret_cast<uint32_t*>(&h1));
    }
    BAR_SYNC(bar_id);

    // ================= main loop =================
    for (int i = 0; i < cnt; ++i) {
        const int j = i & 1;
        const int t = s + i * VSLICES;
        const uint32_t sF = j ? sF1 : sF0;

        // ---- issue cp.async tile i+2 -> S(i&1) (non-blocking) ----
        if (i + 2 < cnt) {
            const uint32_t sS = j ? sS1 : sS0;
            const int nb = (s + (i + 2) * VSLICES) * TILE_M;
            #pragma unroll
            for (int u = 0; u < 8; ++u) {
                int row = u * 8 + rsub;
                int node = nb + row;
                uint32_t sz = (node < n_nodes) ? 16u : 0u;
                int node_c = (node < n_nodes) ? node : 0;
                const char* src = reinterpret_cast<const char*>(
                    x + (((size_t)node_c * M_TOTAL + m) << 7)) + fc * 16;
                CP_ASYNC16(sS + (uint32_t)(row << 9) + (uint32_t)(fc << 4), src, sz);
            }
        }
        CP_COMMIT();   // keep group counts aligned

        // ---- MMA on tile i from F(j) ----
        float acc[2][4][4];
        #pragma unroll
        for (int mt = 0; mt < 2; ++mt)
            #pragma unroll
            for (int nt = 0; nt < 4; ++nt)
                #pragma unroll
                for (int q = 0; q < 4; ++q)
                    acc[mt][nt][q] = 0.0f;

        #pragma unroll
        for (int ks = 0; ks < 8; ++ks) {
            const int ach = (2 * ks + a_hi) ^ a_sw;
            uint32_t a[2][4];
            #pragma unroll
            for (int mt = 0; mt < 2; ++mt)
                LDMATRIX_X4(a[mt][0], a[mt][1], a[mt][2], a[mt][3],
                            sF + aoff[mt] + (uint32_t)(ach << 4));
            #pragma unroll
            for (int mt = 0; mt < 2; ++mt)
                #pragma unroll
                for (int nt = 0; nt < 4; ++nt)
                    MMA16816(acc[mt][nt], a[mt],
                             breg[ks][nt >> 1][(nt & 1) * 2],
                             breg[ks][nt >> 1][(nt & 1) * 2 + 1]);
        }

        // ---- epilogue: store tile i ----
        {
            const int node0 = t * TILE_M;
            const int row_in = lane >> 2;
            const int col_in = (lane & 3) << 1;
            #pragma unroll
            for (int mt = 0; mt < 2; ++mt) {
                #pragma unroll
                for (int q2 = 0; q2 < 2; ++q2) {
                    int node = node0 + wr + mt * 16 + q2 * 8 + row_in;
                    if (node < n_nodes) {
                        float* op = out + (((size_t)node * M_TOTAL + m) << 7)
                                  + wc + col_in;
                        #pragma unroll
                        for (int nt = 0; nt < 4; ++nt) {
                            float2 vv;
                            vv.x = acc[mt][nt][q2 * 2];
                            vv.y = acc[mt][nt][q2 * 2 + 1];
                            *reinterpret_cast<float2*>(op + nt * 8) = vv;
                        }
                    }
                }
            }
        }

        // ---- wait tile i+1, convert S((i+1)&1) -> F((i+1)&1) ----
        CP_WAIT1();
        if (i + 1 < cnt) {
            const uint32_t sSn = j ? sS0 : sS1;
            const uint32_t sFn = j ? sF0 : sF1;
            #pragma unroll
            for (int u = 0; u < 8; ++u) {
                int row = u * 8 + rsub;
                uint32_t r0, r1, r2, r3;
                LDS128(r0, r1, r2, r3, sSn + (uint32_t)(row << 9) + (uint32_t)(fc << 4));
                __half2 h0 = __floats2half2_rn(__uint_as_float(r0), __uint_as_float(r1));
                __half2 h1 = __floats2half2_rn(__uint_as_float(r2), __uint_as_float(r3));
                STS64(sFn + (uint32_t)(row << 8) + swz,
                      *reinterpret_cast<uint32_t*>(&h0),
                      *reinterpret_cast<uint32_t*>(&h1));
            }
        }
        BAR_SYNC(bar_id);
    }
}

// ================= launch =================

extern "C" void kernel_launch(void* const* d_in, const int* in_sizes, int n_in,
                              void* d_out, int out_size) {
    const float* x   = (const float*)d_in[0];
    const float* w   = (const float*)d_in[1];
    const int*   seg = (const int*)d_in[2];
    float* out = (float*)d_out;

    int n_nodes = in_sizes[0] / (M_TOTAL * KDIM);     // 50000
    int ntiles = (n_nodes + TILE_M - 1) / TILE_M;     // 782

    cudaFuncSetAttribute(irreps_dual_kernel,
                         cudaFuncAttributeMaxDynamicSharedMemorySize,
                         2 * GROUP_SMEM);

    irreps_dual_kernel<<<152, THREADS, 2 * GROUP_SMEM>>>(x, w, seg, out,
                                                         n_nodes, ntiles);
}

// round 16
// speedup vs baseline: 1.0834x; 1.0083x over previous
#include <cuda_runtime.h>
#include <cuda_fp16.h>
#include <cstdint>

// ================= config =================
#define THREADS 512        // 2 independent groups of 8 warps (256 thr each)
#define VSLICES 19         // 19 * 16 = 304 virtual CTAs = 152 blocks * 2 groups
#define TILE_M 64          // nodes per tile (per group)
#define KDIM 128
#define NDIM 128
#define M_TOTAL 16
#define NPATH 4
#define GROUP_SMEM 98304u  // F0 16K | F1 16K | S0 32K | S1 32K per group
#define STAGGER_NS 1700    // ~half an iteration: anti-phase the two groups

// ================= helpers =================

__device__ __forceinline__ uint32_t smem_u32(const void* p) {
    uint32_t a;
    asm("{ .reg .u64 t; cvta.to.shared.u64 t, %1; cvt.u32.u64 %0, t; }"
        : "=r"(a) : "l"(p));
    return a;
}

#define BAR_SYNC(ID)                                                       \
    asm volatile("bar.sync %0, 256;" :: "r"(ID) : "memory")

#define LDMATRIX_X4(R0, R1, R2, R3, ADDR)                                  \
    asm volatile("ldmatrix.sync.aligned.m8n8.x4.shared.b16 {%0,%1,%2,%3}, [%4];" \
        : "=r"(R0), "=r"(R1), "=r"(R2), "=r"(R3) : "r"(ADDR))

#define MMA16816(D, A, B0, B1)                                             \
    asm volatile("mma.sync.aligned.m16n8k16.row.col.f32.f16.f16.f32 "      \
        "{%0,%1,%2,%3}, {%4,%5,%6,%7}, {%8,%9}, {%0,%1,%2,%3};"            \
        : "+f"((D)[0]), "+f"((D)[1]), "+f"((D)[2]), "+f"((D)[3])           \
        : "r"((A)[0]), "r"((A)[1]), "r"((A)[2]), "r"((A)[3]),              \
          "r"(B0), "r"(B1))

#define STS64(ADDR, LO, HI)                                                \
    asm volatile("st.shared.v2.b32 [%0], {%1,%2};"                          \
        :: "r"(ADDR), "r"(LO), "r"(HI) : "memory")

#define STS16(ADDR, H)                                                     \
    asm volatile("st.shared.b16 [%0], %1;"                                  \
        :: "r"(ADDR), "h"(H) : "memory")

#define LDS128(R0, R1, R2, R3, ADDR)                                       \
    asm volatile("ld.shared.v4.b32 {%0,%1,%2,%3}, [%4];"                    \
        : "=r"(R0), "=r"(R1), "=r"(R2), "=r"(R3) : "r"(ADDR))

#define CP_ASYNC16(DST, SRC, SZ)                                           \
    asm volatile("cp.async.cg.shared.global [%0], [%1], 16, %2;"            \
        :: "r"(DST), "l"(SRC), "r"(SZ) : "memory")

#define CP_COMMIT() asm volatile("cp.async.commit_group;" ::: "memory")
#define CP_WAIT1()  asm volatile("cp.async.wait_group 1;" ::: "memory")

// ================= main kernel =================
// 152 blocks x 512 threads; two independent 256-thread pipelines per block
// (named barriers), ANTI-PHASED by a one-time ~half-iteration nanosleep on
// group 1 so their MMA and cp.async/convert bursts interleave (as R12's two
// real CTAs did by accident of staggered start).
// smem/group: F0/F1 16KB fp16 (swizzled), S0/S1 32KB fp32 stage.
// per-iter: cp.async(i+2) -> MMA(i) -> epilogue(i) -> wait -> convert(i+1).
// B[p] in registers: breg[8][2][4] = 64 regs/thread.

__global__ void __launch_bounds__(THREADS, 1)
irreps_dual_kernel(const float* __restrict__ x,
                   const float* __restrict__ w,
                   const int* __restrict__ seg,
                   float* __restrict__ out,
                   int n_nodes, int ntiles) {
    extern __shared__ char smem[];

    const int tid = threadIdx.x;
    const int g = tid >> 8;            // group 0 / 1
    const int tg = tid & 255;          // tid within group
    const int lane = tg & 31;
    const int wid = tg >> 5;           // 0..7 within group
    const int bar_id = 1 + g;

    // anti-phase the groups: one-time, amortized over ~41 iterations
    if (g == 1) __nanosleep(STAGGER_NS);

    // virtual CTA: v in [0, 304)
    const int v = (blockIdx.x << 1) | g;
    const int s = v % VSLICES;
    const int m = v / VSLICES;
    const int p = seg[m];

    const uint32_t base = smem_u32(smem) + (uint32_t)g * GROUP_SMEM;
    const uint32_t sF0 = base;
    const uint32_t sF1 = base + 16384u;
    const uint32_t sS0 = base + 32768u;
    const uint32_t sS1 = base + 65536u;

    // warp tile: 32 rows x 32 cols (2x4 warp grid per group, CTA-tile 64x128)
    const int wr = (wid >> 2) * 32;
    const int wc = (wid & 3) * 32;

    const int cnt = (ntiles - s + VSLICES - 1) / VSLICES;

    // staging coords: row = u*8 + rsub (rsub = wid), 16B col = fc (= lane)
    const int fc = lane;
    const int rsub = wid;
    const uint32_t swz = (uint32_t)((((fc >> 1) ^ (rsub & 7)) << 4) | ((fc & 1) << 3));

    // ---- prologue: cp.async tile 0 -> S0 ----
    {
        const int nb = s * TILE_M;
        #pragma unroll
        for (int u = 0; u < 8; ++u) {
            int row = u * 8 + rsub;
            int node = nb + row;
            uint32_t sz = (node < n_nodes) ? 16u : 0u;
            int node_c = (node < n_nodes) ? node : 0;
            const char* src = reinterpret_cast<const char*>(
                x + (((size_t)node_c * M_TOTAL + m) << 7)) + fc * 16;
            CP_ASYNC16(sS0 + (uint32_t)(row << 9) + (uint32_t)(fc << 4), src, sz);
        }
        CP_COMMIT();
    }

    // ---- convert W[p] fp32 [k][n] -> S1 fp16 [n][k] swizzled ----
    {
        const float* wp = w + (p << 14);
        #pragma unroll 8
        for (int i = 0; i < 64; ++i) {
            int e = i * 256 + tg;             // 16384 elements, coalesced
            int k = e >> 7;
            int n = e & 127;
            __half h = __float2half_rn(wp[e]);
            uint32_t off = (uint32_t)(n << 8)
                         + (uint32_t)((((k >> 3) ^ (n & 7)) << 4))
                         + (uint32_t)((k & 7) << 1);
            STS16(sS1 + off, __half_as_ushort(h));
        }
    }
    BAR_SYNC(bar_id);

    // ---- LDSM B fragments into registers ----
    const int b_row = wc + (lane & 7) + ((lane >> 4) << 3);
    const uint32_t b_base = sS1 + (uint32_t)(b_row << 8);
    const int b_sw = b_row & 7;
    const int b_hi = (lane >> 3) & 1;

    uint32_t breg[8][2][4];
    #pragma unroll
    for (int ks = 0; ks < 8; ++ks) {
        const int bch = (2 * ks + b_hi) ^ b_sw;
        #pragma unroll
        for (int nt4 = 0; nt4 < 2; ++nt4)
            LDMATRIX_X4(breg[ks][nt4][0], breg[ks][nt4][1],
                        breg[ks][nt4][2], breg[ks][nt4][3],
                        b_base + (uint32_t)(nt4 << 12) + (uint32_t)(bch << 4));
    }
    BAR_SYNC(bar_id);   // B reads done before S1 reused as stage buffer

    // ---- cp.async tile 1 -> S1 ----
    if (cnt > 1) {
        const int nb = (s + VSLICES) * TILE_M;
        #pragma unroll
        for (int u = 0; u < 8; ++u) {
            int row = u * 8 + rsub;
            int node = nb + row;
            uint32_t sz = (node < n_nodes) ? 16u : 0u;
            int node_c = (node < n_nodes) ? node : 0;
            const char* src = reinterpret_cast<const char*>(
                x + (((size_t)node_c * M_TOTAL + m) << 7)) + fc * 16;
            CP_ASYNC16(sS1 + (uint32_t)(row << 9) + (uint32_t)(fc << 4), src, sz);
        }
    }
    CP_COMMIT();

    // ---- A fragment addressing ----
    const int a_hi = lane >> 4;
    const int a_sw = lane & 7;
    uint32_t aoff[2];
    #pragma unroll
    for (int mt = 0; mt < 2; ++mt)
        aoff[mt] = (uint32_t)((wr + mt * 16 + (lane & 15)) << 8);

    // ---- prologue: convert tile 0 (S0 -> F0) ----
    CP_WAIT1();
    #pragma unroll
    for (int u = 0; u < 8; ++u) {
        int row = u * 8 + rsub;
        uint32_t r0, r1, r2, r3;
        LDS128(r0, r1, r2, r3, sS0 + (uint32_t)(row << 9) + (uint32_t)(fc << 4));
        __half2 h0 = __floats2half2_rn(__uint_as_float(r0), __uint_as_float(r1));
        __half2 h1 = __floats2half2_rn(__uint_as_float(r2), __uint_as_float(r3));
        STS64(sF0 + (uint32_t)(row << 8) + swz,
              *reinterpret_cast<uint32_t*>(&h0),
              *reinterpret_cast<uint32_t*>(&h1));
    }
    BAR_SYNC(bar_id);

    // ================= main loop =================
    for (int i = 0; i < cnt; ++i) {
        const int j = i & 1;
        const int t = s + i * VSLICES;
        const uint32_t sF = j ? sF1 : sF0;

        // ---- issue cp.async tile i+2 -> S(i&1) (non-blocking) ----
        if (i + 2 < cnt) {
            const uint32_t sS = j ? sS1 : sS0;
            const int nb = (s + (i + 2) * VSLICES) * TILE_M;
            #pragma unroll
            for (int u = 0; u < 8; ++u) {
                int row = u * 8 + rsub;
                int node = nb + row;
                uint32_t sz = (node < n_nodes) ? 16u : 0u;
                int node_c = (node < n_nodes) ? node : 0;
                const char* src = reinterpret_cast<const char*>(
                    x + (((size_t)node_c * M_TOTAL + m) << 7)) + fc * 16;
                CP_ASYNC16(sS + (uint32_t)(row << 9) + (uint32_t)(fc << 4), src, sz);
            }
        }
        CP_COMMIT();   // keep group counts aligned

        // ---- MMA on tile i from F(j) ----
        float acc[2][4][4];
        #pragma unroll
        for (int mt = 0; mt < 2; ++mt)
            #pragma unroll
            for (int nt = 0; nt < 4; ++nt)
                #pragma unroll
                for (int q = 0; q < 4; ++q)
                    acc[mt][nt][q] = 0.0f;

        #pragma unroll
        for (int ks = 0; ks < 8; ++ks) {
            const int ach = (2 * ks + a_hi) ^ a_sw;
            uint32_t a[2][4];
            #pragma unroll
            for (int mt = 0; mt < 2; ++mt)
                LDMATRIX_X4(a[mt][0], a[mt][1], a[mt][2], a[mt][3],
                            sF + aoff[mt] + (uint32_t)(ach << 4));
            #pragma unroll
            for (int mt = 0; mt < 2; ++mt)
                #pragma unroll
                for (int nt = 0; nt < 4; ++nt)
                    MMA16816(acc[mt][nt], a[mt],
                             breg[ks][nt >> 1][(nt & 1) * 2],
                             breg[ks][nt >> 1][(nt & 1) * 2 + 1]);
        }

        // ---- epilogue: store tile i ----
        {
            const int node0 = t * TILE_M;
            const int row_in = lane >> 2;
            const int col_in = (lane & 3) << 1;
            #pragma unroll
            for (int mt = 0; mt < 2; ++mt) {
                #pragma unroll
                for (int q2 = 0; q2 < 2; ++q2) {
                    int node = node0 + wr + mt * 16 + q2 * 8 + row_in;
                    if (node < n_nodes) {
                        float* op = out + (((size_t)node * M_TOTAL + m) << 7)
                                  + wc + col_in;
                        #pragma unroll
                        for (int nt = 0; nt < 4; ++nt) {
                            float2 vv;
                            vv.x = acc[mt][nt][q2 * 2];
                            vv.y = acc[mt][nt][q2 * 2 + 1];
                            *reinterpret_cast<float2*>(op + nt * 8) = vv;
                        }
                    }
                }
            }
        }

        // ---- wait tile i+1, convert S((i+1)&1) -> F((i+1)&1) ----
        CP_WAIT1();
        if (i + 1 < cnt) {
            const uint32_t sSn = j ? sS0 : sS1;
            const uint32_t sFn = j ? sF0 : sF1;
            #pragma unroll
            for (int u = 0; u < 8; ++u) {
                int row = u * 8 + rsub;
                uint32_t r0, r1, r2, r3;
                LDS128(r0, r1, r2, r3, sSn + (uint32_t)(row << 9) + (uint32_t)(fc << 4));
                __half2 h0 = __floats2half2_rn(__uint_as_float(r0), __uint_as_float(r1));
                __half2 h1 = __floats2half2_rn(__uint_as_float(r2), __uint_as_float(r3));
                STS64(sFn + (uint32_t)(row << 8) + swz,
                      *reinterpret_cast<uint32_t*>(&h0),
                      *reinterpret_cast<uint32_t*>(&h1));
            }
        }
        BAR_SYNC(bar_id);
    }
}

// ================= launch =================

extern "C" void kernel_launch(void* const* d_in, const int* in_sizes, int n_in,
                              void* d_out, int out_size) {
    const float* x   = (const float*)d_in[0];
    const float* w   = (const float*)d_in[1];
    const int*   seg = (const int*)d_in[2];
    float* out = (float*)d_out;

    int n_nodes = in_sizes[0] / (M_TOTAL * KDIM);     // 50000
    int ntiles = (n_nodes + TILE_M - 1) / TILE_M;     // 782

    cudaFuncSetAttribute(irreps_dual_kernel,
                         cudaFuncAttributeMaxDynamicSharedMemorySize,
                         2 * GROUP_SMEM);

    irreps_dual_kernel<<<152, THREADS, 2 * GROUP_SMEM>>>(x, w, seg, out,
                                                         n_nodes, ntiles);
}